// round 1
// baseline (speedup 1.0000x reference)
#include <cuda_runtime.h>
#include <cuda_bf16.h>
#include <math.h>

// ---------------- problem constants ----------------
constexpr int CB  = 32;     // batch
constexpr int CD  = 384;    // model dim
constexpr int CH  = 8;      // heads
constexpr int CHD = 48;     // head dim
constexpr int CNS = 1024;   // search tokens (32x32)
constexpr int CNT = 256;    // target tokens (16x16)
constexpr int CN  = CNS + CNT;   // 1280
constexpr int CKV = 256 + 64;    // kv tokens per batch (search 16x16 + target 8x8)
constexpr int CFF = 4 * CD;      // 1536
constexpr float CSCALE = 0.14433756729740643f; // 1/sqrt(48)
constexpr float EPS_LN = 1e-5f;
constexpr float EPS_BN = 1e-5f;

// ---------------- scratch (static device allocations; no cudaMalloc) -------
__device__ float g_xn  [(size_t)CB * CN  * CD];
__device__ float g_qc  [(size_t)CB * CN  * CD];
__device__ float g_kc  [(size_t)CB * CKV * CD];
__device__ float g_vc  [(size_t)CB * CKV * CD];
__device__ float g_qp  [(size_t)CB * CN  * CD];
__device__ float g_kp  [(size_t)CB * CKV * CD];
__device__ float g_vp  [(size_t)CB * CKV * CD];
__device__ float g_attn[(size_t)CB * CN  * CD];
__device__ float g_x2  [(size_t)CB * CN  * CD];
__device__ float g_h   [(size_t)CB * CN  * CD];
__device__ float g_ff  [(size_t)CB * CN  * CFF];

// ---------------- LayerNorm 1 : one block (128 thr) per token --------------
__global__ __launch_bounds__(128) void ln1_kernel(
    const float* __restrict__ x, const float* __restrict__ g,
    const float* __restrict__ b, float* __restrict__ out)
{
    const size_t tok = blockIdx.x;
    const int tid = threadIdx.x;
    const float* xp = x + tok * CD;

    float v0 = xp[tid], v1 = xp[tid + 128], v2 = xp[tid + 256];
    float s = v0 + v1 + v2;
    float q = v0 * v0 + v1 * v1 + v2 * v2;
    #pragma unroll
    for (int o = 16; o > 0; o >>= 1) {
        s += __shfl_xor_sync(0xffffffffu, s, o);
        q += __shfl_xor_sync(0xffffffffu, q, o);
    }
    __shared__ float ss[4], sq[4];
    if ((tid & 31) == 0) { ss[tid >> 5] = s; sq[tid >> 5] = q; }
    __syncthreads();
    s = ss[0] + ss[1] + ss[2] + ss[3];
    q = sq[0] + sq[1] + sq[2] + sq[3];
    const float mean = s * (1.0f / CD);
    const float var  = q * (1.0f / CD) - mean * mean;
    const float inv  = rsqrtf(var + EPS_LN);

    float* op = out + tok * CD;
    op[tid]       = (v0 - mean) * inv * g[tid]       + b[tid];
    op[tid + 128] = (v1 - mean) * inv * g[tid + 128] + b[tid + 128];
    op[tid + 256] = (v2 - mean) * inv * g[tid + 256] + b[tid + 256];
}

// --------- residual add + LayerNorm 2 (writes both x2 and ln(x2)) ----------
__global__ __launch_bounds__(128) void addln2_kernel(
    const float* __restrict__ x, const float* __restrict__ attn,
    const float* __restrict__ g, const float* __restrict__ b,
    float* __restrict__ x2, float* __restrict__ out)
{
    const size_t tok = blockIdx.x;
    const int tid = threadIdx.x;
    const float* xp = x    + tok * CD;
    const float* ap = attn + tok * CD;

    float v0 = xp[tid]       + ap[tid];
    float v1 = xp[tid + 128] + ap[tid + 128];
    float v2 = xp[tid + 256] + ap[tid + 256];
    float* x2p = x2 + tok * CD;
    x2p[tid] = v0; x2p[tid + 128] = v1; x2p[tid + 256] = v2;

    float s = v0 + v1 + v2;
    float q = v0 * v0 + v1 * v1 + v2 * v2;
    #pragma unroll
    for (int o = 16; o > 0; o >>= 1) {
        s += __shfl_xor_sync(0xffffffffu, s, o);
        q += __shfl_xor_sync(0xffffffffu, q, o);
    }
    __shared__ float ss[4], sq[4];
    if ((tid & 31) == 0) { ss[tid >> 5] = s; sq[tid >> 5] = q; }
    __syncthreads();
    s = ss[0] + ss[1] + ss[2] + ss[3];
    q = sq[0] + sq[1] + sq[2] + sq[3];
    const float mean = s * (1.0f / CD);
    const float var  = q * (1.0f / CD) - mean * mean;
    const float inv  = rsqrtf(var + EPS_LN);

    float* op = out + tok * CD;
    op[tid]       = (v0 - mean) * inv * g[tid]       + b[tid];
    op[tid + 128] = (v1 - mean) * inv * g[tid + 128] + b[tid + 128];
    op[tid + 256] = (v2 - mean) * inv * g[tid + 256] + b[tid + 256];
}

// ----- depthwise 3x3 conv stride 1 pad 1 + bias + BN-fold (Q path) ---------
// grid (CN, CB), block CD
__global__ __launch_bounds__(CD) void convq_kernel(
    const float* __restrict__ xn, const float* __restrict__ w,
    const float* __restrict__ cb, const float* __restrict__ bg,
    const float* __restrict__ bb, float* __restrict__ out)
{
    const int t = blockIdx.x, bidx = blockIdx.y, d = threadIdx.x;
    int hw, loc, base;
    if (t < CNS) { hw = 32; loc = t;        base = 0;   }
    else         { hw = 16; loc = t - CNS;  base = CNS; }
    const int oy = loc / hw, ox = loc % hw;

    float s = 0.f;
    #pragma unroll
    for (int ky = 0; ky < 3; ky++) {
        const int iy = oy + ky - 1;
        if ((unsigned)iy >= (unsigned)hw) continue;
        #pragma unroll
        for (int kx = 0; kx < 3; kx++) {
            const int ix = ox + kx - 1;
            if ((unsigned)ix >= (unsigned)hw) continue;
            s += w[d * 9 + ky * 3 + kx] *
                 xn[((size_t)bidx * CN + base + iy * hw + ix) * CD + d];
        }
    }
    const float sc = bg[d] * rsqrtf(1.0f + EPS_BN);
    out[((size_t)bidx * CN + t) * CD + d] = (s + cb[d]) * sc + bb[d];
}

// ----- depthwise 3x3 conv stride 2 pad 1, K and V simultaneously -----------
// grid (CKV, CB), block CD. kv tokens: [0,256)=search 16x16, [256,320)=target 8x8
__global__ __launch_bounds__(CD) void convkv_kernel(
    const float* __restrict__ xn,
    const float* __restrict__ wk, const float* __restrict__ cbk,
    const float* __restrict__ bgk, const float* __restrict__ bbk,
    const float* __restrict__ wv, const float* __restrict__ cbv,
    const float* __restrict__ bgv, const float* __restrict__ bbv,
    float* __restrict__ outk, float* __restrict__ outv)
{
    const int t = blockIdx.x, bidx = blockIdx.y, d = threadIdx.x;
    int hwin, hwout, loc, base;
    if (t < 256) { hwin = 32; hwout = 16; loc = t;       base = 0;   }
    else         { hwin = 16; hwout = 8;  loc = t - 256; base = CNS; }
    const int oy = loc / hwout, ox = loc % hwout;

    float sk = 0.f, sv = 0.f;
    #pragma unroll
    for (int ky = 0; ky < 3; ky++) {
        const int iy = 2 * oy + ky - 1;
        if ((unsigned)iy >= (unsigned)hwin) continue;
        #pragma unroll
        for (int kx = 0; kx < 3; kx++) {
            const int ix = 2 * ox + kx - 1;
            if ((unsigned)ix >= (unsigned)hwin) continue;
            const float xv = xn[((size_t)bidx * CN + base + iy * hwin + ix) * CD + d];
            sk += wk[d * 9 + ky * 3 + kx] * xv;
            sv += wv[d * 9 + ky * 3 + kx] * xv;
        }
    }
    const size_t o = ((size_t)bidx * CKV + t) * CD + d;
    outk[o] = (sk + cbk[d]) * (bgk[d] * rsqrtf(1.0f + EPS_BN)) + bbk[d];
    outv[o] = (sv + cbv[d]) * (bgv[d] * rsqrtf(1.0f + EPS_BN)) + bbv[d];
}

// ---------------- generic fp32 tiled GEMM: C = A(MxK) * W(NxK)^T + bias ----
// EPI: 0 = none, 1 = exact GELU, 2 = add residual (res, same layout as C)
// 64x64 block tile, BK=16, 256 threads, 4x4 per thread. M,N,K all tile-exact.
template <int EPI>
__global__ __launch_bounds__(256) void gemm_kernel(
    const float* __restrict__ A, const float* __restrict__ W,
    const float* __restrict__ bias, const float* __restrict__ res,
    float* __restrict__ C, int M, int NC, int K)
{
    __shared__ float As[16][68];
    __shared__ float Ws[16][68];
    const int tid = threadIdx.x;
    const int tx = tid & 15, ty = tid >> 4;
    const int lr = tid >> 2;          // 0..63
    const int lc = (tid & 3) << 2;    // 0,4,8,12

    const float* Ap = A + (size_t)(blockIdx.y * 64 + lr) * K + lc;
    const float* Wp = W + (size_t)(blockIdx.x * 64 + lr) * K + lc;

    float acc[4][4] = {};
    for (int k0 = 0; k0 < K; k0 += 16) {
        const float4 a4 = *(const float4*)(Ap + k0);
        const float4 w4 = *(const float4*)(Wp + k0);
        As[lc + 0][lr] = a4.x; As[lc + 1][lr] = a4.y;
        As[lc + 2][lr] = a4.z; As[lc + 3][lr] = a4.w;
        Ws[lc + 0][lr] = w4.x; Ws[lc + 1][lr] = w4.y;
        Ws[lc + 2][lr] = w4.z; Ws[lc + 3][lr] = w4.w;
        __syncthreads();
        #pragma unroll
        for (int k = 0; k < 16; k++) {
            const float4 av = *(const float4*)&As[k][ty << 2];
            const float4 wv = *(const float4*)&Ws[k][tx << 2];
            const float a[4] = {av.x, av.y, av.z, av.w};
            const float w[4] = {wv.x, wv.y, wv.z, wv.w};
            #pragma unroll
            for (int i = 0; i < 4; i++)
                #pragma unroll
                for (int j = 0; j < 4; j++)
                    acc[i][j] += a[i] * w[j];
        }
        __syncthreads();
    }

    #pragma unroll
    for (int i = 0; i < 4; i++) {
        const int row = blockIdx.y * 64 + (ty << 2) + i;
        #pragma unroll
        for (int j = 0; j < 4; j++) {
            const int col = blockIdx.x * 64 + (tx << 2) + j;
            float v = acc[i][j] + bias[col];
            if (EPI == 1) v = 0.5f * v * (1.0f + erff(v * 0.70710678118654752f));
            if (EPI == 2) v += res[(size_t)row * NC + col];
            C[(size_t)row * NC + col] = v;
        }
    }
}

// ---------------- attention: 1 thread per query, online softmax ------------
// q/k/v are [B, tok, D] with head slice at column h*48. 64-key smem chunks.
// grid: (numQ/128, CH, CB), block 128.
__global__ __launch_bounds__(128) void attn_kernel(
    const float* __restrict__ qp, const float* __restrict__ kp,
    const float* __restrict__ vp, float* __restrict__ out,
    int qTokBase, int kvStart, int numKV)
{
    const int b = blockIdx.z, h = blockIdx.y;
    const int t = qTokBase + blockIdx.x * 128 + threadIdx.x;

    __shared__ float Ks[64][CHD];
    __shared__ float Vs[64][CHD];

    float qr[CHD], o[CHD];
    const float* qptr = qp + ((size_t)b * CN + t) * CD + h * CHD;
    #pragma unroll
    for (int d = 0; d < CHD; d++) { qr[d] = qptr[d] * CSCALE; o[d] = 0.f; }
    float m = -1e30f, l = 0.f;

    for (int j0 = 0; j0 < numKV; j0 += 64) {
        // cooperative load of 64 keys + values (numKV is a multiple of 64)
        for (int idx = threadIdx.x; idx < 64 * CHD; idx += 128) {
            const int j = idx / CHD, d = idx % CHD;
            const size_t off = ((size_t)b * CKV + kvStart + j0 + j) * CD + h * CHD + d;
            Ks[j][d] = kp[off];
            Vs[j][d] = vp[off];
        }
        __syncthreads();
        for (int j = 0; j < 64; j++) {
            float s = 0.f;
            #pragma unroll
            for (int d = 0; d < CHD; d++) s += qr[d] * Ks[j][d];
            if (s <= m) {
                const float p = expf(s - m);
                l += p;
                #pragma unroll
                for (int d = 0; d < CHD; d++) o[d] += p * Vs[j][d];
            } else {
                const float c = expf(m - s);
                m = s;
                l = l * c + 1.f;
                #pragma unroll
                for (int d = 0; d < CHD; d++) o[d] = o[d] * c + Vs[j][d];
            }
        }
        __syncthreads();
    }

    const float inv = 1.0f / l;
    float* op = out + ((size_t)b * CN + t) * CD + h * CHD;
    #pragma unroll
    for (int d = 0; d < CHD; d++) op[d] = o[d] * inv;
}

// ---------------- launch ----------------
extern "C" void kernel_launch(void* const* d_in, const int* in_sizes, int n_in,
                              void* d_out, int out_size)
{
    const float* x     = (const float*)d_in[0];
    const float* ln1_g = (const float*)d_in[1];
    const float* ln1_b = (const float*)d_in[2];
    const float* dwq_w = (const float*)d_in[3];
    const float* dwq_b = (const float*)d_in[4];
    const float* bnq_g = (const float*)d_in[5];
    const float* bnq_b = (const float*)d_in[6];
    const float* dwk_w = (const float*)d_in[7];
    const float* dwk_b = (const float*)d_in[8];
    const float* bnk_g = (const float*)d_in[9];
    const float* bnk_b = (const float*)d_in[10];
    const float* dwv_w = (const float*)d_in[11];
    const float* dwv_b = (const float*)d_in[12];
    const float* bnv_g = (const float*)d_in[13];
    const float* bnv_b = (const float*)d_in[14];
    const float* pq_w  = (const float*)d_in[15];
    const float* pq_b  = (const float*)d_in[16];
    const float* pk_w  = (const float*)d_in[17];
    const float* pk_b  = (const float*)d_in[18];
    const float* pv_w  = (const float*)d_in[19];
    const float* pv_b  = (const float*)d_in[20];
    const float* ln2_g = (const float*)d_in[21];
    const float* ln2_b = (const float*)d_in[22];
    const float* ff1_w = (const float*)d_in[23];
    const float* ff1_b = (const float*)d_in[24];
    const float* ff2_w = (const float*)d_in[25];
    const float* ff2_b = (const float*)d_in[26];
    float* out = (float*)d_out;

    float *xn, *qc, *kc, *vc, *qpb, *kpb, *vpb, *attnb, *x2b, *hb, *ffb;
    cudaGetSymbolAddress((void**)&xn,    g_xn);
    cudaGetSymbolAddress((void**)&qc,    g_qc);
    cudaGetSymbolAddress((void**)&kc,    g_kc);
    cudaGetSymbolAddress((void**)&vc,    g_vc);
    cudaGetSymbolAddress((void**)&qpb,   g_qp);
    cudaGetSymbolAddress((void**)&kpb,   g_kp);
    cudaGetSymbolAddress((void**)&vpb,   g_vp);
    cudaGetSymbolAddress((void**)&attnb, g_attn);
    cudaGetSymbolAddress((void**)&x2b,   g_x2);
    cudaGetSymbolAddress((void**)&hb,    g_h);
    cudaGetSymbolAddress((void**)&ffb,   g_ff);

    // 1. LN1
    ln1_kernel<<<CB * CN, 128>>>(x, ln1_g, ln1_b, xn);

    // 2. depthwise convs (+bias +BN fold)
    convq_kernel<<<dim3(CN, CB), CD>>>(xn, dwq_w, dwq_b, bnq_g, bnq_b, qc);
    convkv_kernel<<<dim3(CKV, CB), CD>>>(xn, dwk_w, dwk_b, bnk_g, bnk_b,
                                         dwv_w, dwv_b, bnv_g, bnv_b, kc, vc);

    // 3. QKV projections (output stays [B,tok,D]; head slice = columns h*48..)
    gemm_kernel<0><<<dim3(CD / 64, CB * CN / 64), 256>>>(
        qc, pq_w, pq_b, nullptr, qpb, CB * CN, CD, CD);
    gemm_kernel<0><<<dim3(CD / 64, CB * CKV / 64), 256>>>(
        kc, pk_w, pk_b, nullptr, kpb, CB * CKV, CD, CD);
    gemm_kernel<0><<<dim3(CD / 64, CB * CKV / 64), 256>>>(
        vc, pv_w, pv_b, nullptr, vpb, CB * CKV, CD, CD);

    // 4. attention: search queries -> mixed kv (all 320), target queries -> target kv
    attn_kernel<<<dim3(CNS / 128, CH, CB), 128>>>(qpb, kpb, vpb, attnb, 0, 0, 320);
    attn_kernel<<<dim3(CNT / 128, CH, CB), 128>>>(qpb, kpb, vpb, attnb, CNS, 256, 64);

    // 5. residual + LN2
    addln2_kernel<<<CB * CN, 128>>>(x, attnb, ln2_g, ln2_b, x2b, hb);

    // 6. FFN: GELU(h @ ff1^T + b1) @ ff2^T + b2 + x2  -> d_out
    gemm_kernel<1><<<dim3(CFF / 64, CB * CN / 64), 256>>>(
        hb, ff1_w, ff1_b, nullptr, ffb, CB * CN, CFF, CD);
    gemm_kernel<2><<<dim3(CD / 64, CB * CN / 64), 256>>>(
        ffb, ff2_w, ff2_b, x2b, out, CB * CN, CD, CFF);
}

// round 4
// speedup vs baseline: 2.1142x; 2.1142x over previous
#include <cuda_runtime.h>
#include <cuda_bf16.h>
#include <math.h>
#include <stdint.h>

// ---------------- problem constants ----------------
constexpr int CB  = 32;
constexpr int CD  = 384;
constexpr int CH  = 8;
constexpr int CHD = 48;
constexpr int CNS = 1024;
constexpr int CNT = 256;
constexpr int CN  = CNS + CNT;   // 1280
constexpr int CKV = 256 + 64;    // 320
constexpr int CFF = 4 * CD;      // 1536
constexpr float CSCALE = 0.14433756729740643f;
constexpr float EPS_LN = 1e-5f;
constexpr float EPS_BN = 1e-5f;

// ---------------- scratch ----------------
__device__ float g_xn  [(size_t)CB * CN  * CD];
__device__ float g_qc  [(size_t)CB * CN  * CD];
__device__ float g_kc  [(size_t)CB * CKV * CD];
__device__ float g_vc  [(size_t)CB * CKV * CD];
__device__ float g_qp  [(size_t)CB * CN  * CD];
__device__ float g_kp  [(size_t)CB * CKV * CD];
__device__ float g_vp  [(size_t)CB * CKV * CD];
__device__ float g_attn[(size_t)CB * CN  * CD];
__device__ float g_x2  [(size_t)CB * CN  * CD];
__device__ float g_h   [(size_t)CB * CN  * CD];
__device__ float g_ff  [(size_t)CB * CN  * CFF];
// tf32-rounded weights
__device__ float g_wpq [(size_t)CD * CD];
__device__ float g_wpk [(size_t)CD * CD];
__device__ float g_wpv [(size_t)CD * CD];
__device__ float g_wf1 [(size_t)CFF * CD];
__device__ float g_wf2 [(size_t)CD * CFF];

// ---------------- helpers ----------------
__device__ __forceinline__ float tf32r(float x) {
    uint32_t u;
    asm("cvt.rna.tf32.f32 %0, %1;" : "=r"(u) : "f"(x));
    return __uint_as_float(u);
}
__device__ __forceinline__ uint32_t smem_u32(const void* p) {
    uint32_t a;
    asm("{ .reg .u64 t; cvta.to.shared.u64 t, %1; cvt.u32.u64 %0, t; }" : "=r"(a) : "l"(p));
    return a;
}
__device__ __forceinline__ void cp_async16(uint32_t dst, const void* src) {
    asm volatile("cp.async.cg.shared.global [%0], [%1], 16;" :: "r"(dst), "l"(src) : "memory");
}
__device__ __forceinline__ void cp_commit() {
    asm volatile("cp.async.commit_group;" ::: "memory");
}
template <int N>
__device__ __forceinline__ void cp_wait() {
    asm volatile("cp.async.wait_group %0;" :: "n"(N) : "memory");
}
__device__ __forceinline__ void mma_tf32(float* c, const uint32_t* a, const uint32_t* b) {
    asm volatile(
        "mma.sync.aligned.m16n8k8.row.col.f32.tf32.tf32.f32 "
        "{%0,%1,%2,%3}, {%4,%5,%6,%7}, {%8,%9}, {%0,%1,%2,%3};"
        : "+f"(c[0]), "+f"(c[1]), "+f"(c[2]), "+f"(c[3])
        : "r"(a[0]), "r"(a[1]), "r"(a[2]), "r"(a[3]), "r"(b[0]), "r"(b[1]));
}

// round a tensor to tf32 (RN) into scratch
__global__ void round_tf32_kernel(const float* __restrict__ src, float* __restrict__ dst, int n) {
    int i = blockIdx.x * 256 + threadIdx.x;
    if (i < n) dst[i] = tf32r(src[i]);
}

// ---------------- mma.sync tf32 GEMM: C = A(MxK) @ W(NxK)^T + bias ----------
// EPI: 0 none, 1 exact GELU (output rounded to tf32), 2 +residual.
// grid (N/128, M/128), 256 threads = 8 warps (2 x 4), warp tile 64x32.
// A and W must already be tf32-rounded.
constexpr int GP = 36;               // padded stride (floats), 144 B, 16B aligned
constexpr int GTILE = 128 * GP;      // floats per buffer
constexpr int GSMEM_BYTES = 4 * GTILE * 4;   // A0,A1,B0,B1 = 73728 B

template <int EPI>
__global__ __launch_bounds__(256) void gemm_mma(
    const float* __restrict__ A, const float* __restrict__ W,
    const float* __restrict__ bias, const float* __restrict__ res,
    float* __restrict__ C, int M, int NC, int K)
{
    extern __shared__ __align__(16) float smem[];
    float* As[2] = { smem,             smem + GTILE };
    float* Bs[2] = { smem + 2 * GTILE, smem + 3 * GTILE };

    const int tid  = threadIdx.x;
    const int wid  = tid >> 5;
    const int lane = tid & 31;
    const int gid  = lane >> 2;      // 0..7
    const int tig  = lane & 3;       // 0..3
    const int wr   = wid >> 2;       // 0..1  (64-row slab)
    const int wc   = wid & 3;        // 0..3  (32-col slab)

    const float* Ap = A + (size_t)blockIdx.y * 128 * K;
    const float* Wp = W + (size_t)blockIdx.x * 128 * K;

    // cp.async tile loader: 1024 16B-chunks per operand, 4 per thread
    auto load_tile = [&](int kt, int buf) {
        const uint32_t abase = smem_u32(As[buf]);
        const uint32_t bbase = smem_u32(Bs[buf]);
        #pragma unroll
        for (int i = 0; i < 4; i++) {
            const int c   = tid + i * 256;        // 0..1023
            const int row = c >> 3;
            const int kg  = c & 7;                // float4 index within 32
            const uint32_t doff = (row * GP + kg * 4) * 4;
            cp_async16(abase + doff, Ap + (size_t)row * K + kt * 32 + kg * 4);
            cp_async16(bbase + doff, Wp + (size_t)row * K + kt * 32 + kg * 4);
        }
        cp_commit();
    };

    float acc[4][4][4] = {};   // [mi][ni][reg]

    const int nk = K >> 5;
    load_tile(0, 0);

    for (int kt = 0; kt < nk; kt++) {
        const int cur = kt & 1;
        if (kt + 1 < nk) { load_tile(kt + 1, 1 - cur); cp_wait<1>(); }
        else             { cp_wait<0>(); }
        __syncthreads();

        const float* Ab = As[cur];
        const float* Bb = Bs[cur];
        #pragma unroll
        for (int ks = 0; ks < 4; ks++) {
            uint32_t af[4][4], bf[4][2];
            #pragma unroll
            for (int mi = 0; mi < 4; mi++) {
                const int r0 = wr * 64 + mi * 16 + gid;
                const int k0 = ks * 8 + tig;
                af[mi][0] = __float_as_uint(Ab[r0 * GP + k0]);
                af[mi][1] = __float_as_uint(Ab[(r0 + 8) * GP + k0]);
                af[mi][2] = __float_as_uint(Ab[r0 * GP + k0 + 4]);
                af[mi][3] = __float_as_uint(Ab[(r0 + 8) * GP + k0 + 4]);
            }
            #pragma unroll
            for (int ni = 0; ni < 4; ni++) {
                const int n0 = wc * 32 + ni * 8 + gid;
                const int k0 = ks * 8 + tig;
                bf[ni][0] = __float_as_uint(Bb[n0 * GP + k0]);
                bf[ni][1] = __float_as_uint(Bb[n0 * GP + k0 + 4]);
            }
            #pragma unroll
            for (int mi = 0; mi < 4; mi++)
                #pragma unroll
                for (int ni = 0; ni < 4; ni++)
                    mma_tf32(acc[mi][ni], af[mi], bf[ni]);
        }
        __syncthreads();
    }

    // epilogue: c0,c1 at (row, 2tig), (row, 2tig+1); c2,c3 at row+8
    const int rbase = blockIdx.y * 128 + wr * 64;
    const int cbase = blockIdx.x * 128 + wc * 32;
    #pragma unroll
    for (int mi = 0; mi < 4; mi++) {
        #pragma unroll
        for (int ni = 0; ni < 4; ni++) {
            const int col = cbase + ni * 8 + 2 * tig;
            const float b0 = bias[col], b1 = bias[col + 1];
            #pragma unroll
            for (int h = 0; h < 2; h++) {
                const int row = rbase + mi * 16 + gid + h * 8;
                float v0 = acc[mi][ni][2 * h + 0] + b0;
                float v1 = acc[mi][ni][2 * h + 1] + b1;
                if (EPI == 1) {
                    v0 = 0.5f * v0 * (1.0f + erff(v0 * 0.70710678118654752f));
                    v1 = 0.5f * v1 * (1.0f + erff(v1 * 0.70710678118654752f));
                    v0 = tf32r(v0); v1 = tf32r(v1);   // feeds next tf32 GEMM
                }
                if (EPI == 2) {
                    const float* rp = res + (size_t)row * NC + col;
                    v0 += rp[0]; v1 += rp[1];
                }
                float2* cp = (float2*)(C + (size_t)row * NC + col);
                *cp = make_float2(v0, v1);
            }
        }
    }
}

// ---------------- LayerNorm 1 ----------------
__global__ __launch_bounds__(128) void ln1_kernel(
    const float* __restrict__ x, const float* __restrict__ g,
    const float* __restrict__ b, float* __restrict__ out)
{
    const size_t tok = blockIdx.x;
    const int tid = threadIdx.x;
    const float* xp = x + tok * CD;

    float v0 = xp[tid], v1 = xp[tid + 128], v2 = xp[tid + 256];
    float s = v0 + v1 + v2;
    float q = v0 * v0 + v1 * v1 + v2 * v2;
    #pragma unroll
    for (int o = 16; o > 0; o >>= 1) {
        s += __shfl_xor_sync(0xffffffffu, s, o);
        q += __shfl_xor_sync(0xffffffffu, q, o);
    }
    __shared__ float ss[4], sq[4];
    if ((tid & 31) == 0) { ss[tid >> 5] = s; sq[tid >> 5] = q; }
    __syncthreads();
    s = ss[0] + ss[1] + ss[2] + ss[3];
    q = sq[0] + sq[1] + sq[2] + sq[3];
    const float mean = s * (1.0f / CD);
    const float var  = q * (1.0f / CD) - mean * mean;
    const float inv  = rsqrtf(var + EPS_LN);

    float* op = out + tok * CD;
    op[tid]       = (v0 - mean) * inv * g[tid]       + b[tid];
    op[tid + 128] = (v1 - mean) * inv * g[tid + 128] + b[tid + 128];
    op[tid + 256] = (v2 - mean) * inv * g[tid + 256] + b[tid + 256];
}

// --------- residual add + LayerNorm 2 (hb output tf32-rounded for FF1) -----
__global__ __launch_bounds__(128) void addln2_kernel(
    const float* __restrict__ x, const float* __restrict__ attn,
    const float* __restrict__ g, const float* __restrict__ b,
    float* __restrict__ x2, float* __restrict__ out)
{
    const size_t tok = blockIdx.x;
    const int tid = threadIdx.x;
    const float* xp = x    + tok * CD;
    const float* ap = attn + tok * CD;

    float v0 = xp[tid]       + ap[tid];
    float v1 = xp[tid + 128] + ap[tid + 128];
    float v2 = xp[tid + 256] + ap[tid + 256];
    float* x2p = x2 + tok * CD;
    x2p[tid] = v0; x2p[tid + 128] = v1; x2p[tid + 256] = v2;

    float s = v0 + v1 + v2;
    float q = v0 * v0 + v1 * v1 + v2 * v2;
    #pragma unroll
    for (int o = 16; o > 0; o >>= 1) {
        s += __shfl_xor_sync(0xffffffffu, s, o);
        q += __shfl_xor_sync(0xffffffffu, q, o);
    }
    __shared__ float ss[4], sq[4];
    if ((tid & 31) == 0) { ss[tid >> 5] = s; sq[tid >> 5] = q; }
    __syncthreads();
    s = ss[0] + ss[1] + ss[2] + ss[3];
    q = sq[0] + sq[1] + sq[2] + sq[3];
    const float mean = s * (1.0f / CD);
    const float var  = q * (1.0f / CD) - mean * mean;
    const float inv  = rsqrtf(var + EPS_LN);

    float* op = out + tok * CD;
    op[tid]       = tf32r((v0 - mean) * inv * g[tid]       + b[tid]);
    op[tid + 128] = tf32r((v1 - mean) * inv * g[tid + 128] + b[tid + 128]);
    op[tid + 256] = tf32r((v2 - mean) * inv * g[tid + 256] + b[tid + 256]);
}

// ----- depthwise 3x3 conv stride 1 pad 1 (Q path), output tf32-rounded -----
__global__ __launch_bounds__(CD) void convq_kernel(
    const float* __restrict__ xn, const float* __restrict__ w,
    const float* __restrict__ cb, const float* __restrict__ bg,
    const float* __restrict__ bb, float* __restrict__ out)
{
    const int t = blockIdx.x, bidx = blockIdx.y, d = threadIdx.x;
    int hw, loc, base;
    if (t < CNS) { hw = 32; loc = t;        base = 0;   }
    else         { hw = 16; loc = t - CNS;  base = CNS; }
    const int oy = loc / hw, ox = loc % hw;

    float s = 0.f;
    #pragma unroll
    for (int ky = 0; ky < 3; ky++) {
        const int iy = oy + ky - 1;
        if ((unsigned)iy >= (unsigned)hw) continue;
        #pragma unroll
        for (int kx = 0; kx < 3; kx++) {
            const int ix = ox + kx - 1;
            if ((unsigned)ix >= (unsigned)hw) continue;
            s += w[d * 9 + ky * 3 + kx] *
                 xn[((size_t)bidx * CN + base + iy * hw + ix) * CD + d];
        }
    }
    const float sc = bg[d] * rsqrtf(1.0f + EPS_BN);
    out[((size_t)bidx * CN + t) * CD + d] = tf32r((s + cb[d]) * sc + bb[d]);
}

// ----- depthwise 3x3 conv stride 2 pad 1, K & V, outputs tf32-rounded ------
__global__ __launch_bounds__(CD) void convkv_kernel(
    const float* __restrict__ xn,
    const float* __restrict__ wk, const float* __restrict__ cbk,
    const float* __restrict__ bgk, const float* __restrict__ bbk,
    const float* __restrict__ wv, const float* __restrict__ cbv,
    const float* __restrict__ bgv, const float* __restrict__ bbv,
    float* __restrict__ outk, float* __restrict__ outv)
{
    const int t = blockIdx.x, bidx = blockIdx.y, d = threadIdx.x;
    int hwin, hwout, loc, base;
    if (t < 256) { hwin = 32; hwout = 16; loc = t;       base = 0;   }
    else         { hwin = 16; hwout = 8;  loc = t - 256; base = CNS; }
    const int oy = loc / hwout, ox = loc % hwout;

    float sk = 0.f, sv = 0.f;
    #pragma unroll
    for (int ky = 0; ky < 3; ky++) {
        const int iy = 2 * oy + ky - 1;
        if ((unsigned)iy >= (unsigned)hwin) continue;
        #pragma unroll
        for (int kx = 0; kx < 3; kx++) {
            const int ix = 2 * ox + kx - 1;
            if ((unsigned)ix >= (unsigned)hwin) continue;
            const float xv = xn[((size_t)bidx * CN + base + iy * hwin + ix) * CD + d];
            sk += wk[d * 9 + ky * 3 + kx] * xv;
            sv += wv[d * 9 + ky * 3 + kx] * xv;
        }
    }
    const size_t o = ((size_t)bidx * CKV + t) * CD + d;
    outk[o] = tf32r((sk + cbk[d]) * (bgk[d] * rsqrtf(1.0f + EPS_BN)) + bbk[d]);
    outv[o] = tf32r((sv + cbv[d]) * (bgv[d] * rsqrtf(1.0f + EPS_BN)) + bbv[d]);
}

// ---------------- attention: 1 thread per query, online softmax ------------
__global__ __launch_bounds__(128) void attn_kernel(
    const float* __restrict__ qp, const float* __restrict__ kp,
    const float* __restrict__ vp, float* __restrict__ out,
    int qTokBase, int kvStart, int numKV)
{
    const int b = blockIdx.z, h = blockIdx.y;
    const int t = qTokBase + blockIdx.x * 128 + threadIdx.x;

    __shared__ float Ks[64][CHD];
    __shared__ float Vs[64][CHD];

    float qr[CHD], o[CHD];
    const float* qptr = qp + ((size_t)b * CN + t) * CD + h * CHD;
    #pragma unroll
    for (int d = 0; d < CHD; d++) { qr[d] = qptr[d] * CSCALE; o[d] = 0.f; }
    float m = -1e30f, l = 0.f;

    for (int j0 = 0; j0 < numKV; j0 += 64) {
        for (int idx = threadIdx.x; idx < 64 * CHD; idx += 128) {
            const int j = idx / CHD, d = idx % CHD;
            const size_t off = ((size_t)b * CKV + kvStart + j0 + j) * CD + h * CHD + d;
            Ks[j][d] = kp[off];
            Vs[j][d] = vp[off];
        }
        __syncthreads();
        for (int j = 0; j < 64; j++) {
            float s = 0.f;
            #pragma unroll
            for (int d = 0; d < CHD; d++) s += qr[d] * Ks[j][d];
            if (s <= m) {
                const float p = expf(s - m);
                l += p;
                #pragma unroll
                for (int d = 0; d < CHD; d++) o[d] += p * Vs[j][d];
            } else {
                const float c = expf(m - s);
                m = s;
                l = l * c + 1.f;
                #pragma unroll
                for (int d = 0; d < CHD; d++) o[d] = o[d] * c + Vs[j][d];
            }
        }
        __syncthreads();
    }

    const float inv = 1.0f / l;
    float* op = out + ((size_t)b * CN + t) * CD + h * CHD;
    #pragma unroll
    for (int d = 0; d < CHD; d++) op[d] = o[d] * inv;
}

// ---------------- launch ----------------
extern "C" void kernel_launch(void* const* d_in, const int* in_sizes, int n_in,
                              void* d_out, int out_size)
{
    const float* x     = (const float*)d_in[0];
    const float* ln1_g = (const float*)d_in[1];
    const float* ln1_b = (const float*)d_in[2];
    const float* dwq_w = (const float*)d_in[3];
    const float* dwq_b = (const float*)d_in[4];
    const float* bnq_g = (const float*)d_in[5];
    const float* bnq_b = (const float*)d_in[6];
    const float* dwk_w = (const float*)d_in[7];
    const float* dwk_b = (const float*)d_in[8];
    const float* bnk_g = (const float*)d_in[9];
    const float* bnk_b = (const float*)d_in[10];
    const float* dwv_w = (const float*)d_in[11];
    const float* dwv_b = (const float*)d_in[12];
    const float* bnv_g = (const float*)d_in[13];
    const float* bnv_b = (const float*)d_in[14];
    const float* pq_w  = (const float*)d_in[15];
    const float* pq_b  = (const float*)d_in[16];
    const float* pk_w  = (const float*)d_in[17];
    const float* pk_b  = (const float*)d_in[18];
    const float* pv_w  = (const float*)d_in[19];
    const float* pv_b  = (const float*)d_in[20];
    const float* ln2_g = (const float*)d_in[21];
    const float* ln2_b = (const float*)d_in[22];
    const float* ff1_w = (const float*)d_in[23];
    const float* ff1_b = (const float*)d_in[24];
    const float* ff2_w = (const float*)d_in[25];
    const float* ff2_b = (const float*)d_in[26];
    float* out = (float*)d_out;

    float *xn, *qc, *kc, *vc, *qpb, *kpb, *vpb, *attnb, *x2b, *hb, *ffb;
    float *wpq, *wpk, *wpv, *wf1, *wf2;
    cudaGetSymbolAddress((void**)&xn,    g_xn);
    cudaGetSymbolAddress((void**)&qc,    g_qc);
    cudaGetSymbolAddress((void**)&kc,    g_kc);
    cudaGetSymbolAddress((void**)&vc,    g_vc);
    cudaGetSymbolAddress((void**)&qpb,   g_qp);
    cudaGetSymbolAddress((void**)&kpb,   g_kp);
    cudaGetSymbolAddress((void**)&vpb,   g_vp);
    cudaGetSymbolAddress((void**)&attnb, g_attn);
    cudaGetSymbolAddress((void**)&x2b,   g_x2);
    cudaGetSymbolAddress((void**)&hb,    g_h);
    cudaGetSymbolAddress((void**)&ffb,   g_ff);
    cudaGetSymbolAddress((void**)&wpq,   g_wpq);
    cudaGetSymbolAddress((void**)&wpk,   g_wpk);
    cudaGetSymbolAddress((void**)&wpv,   g_wpv);
    cudaGetSymbolAddress((void**)&wf1,   g_wf1);
    cudaGetSymbolAddress((void**)&wf2,   g_wf2);

    cudaFuncSetAttribute(gemm_mma<0>, cudaFuncAttributeMaxDynamicSharedMemorySize, GSMEM_BYTES);
    cudaFuncSetAttribute(gemm_mma<1>, cudaFuncAttributeMaxDynamicSharedMemorySize, GSMEM_BYTES);
    cudaFuncSetAttribute(gemm_mma<2>, cudaFuncAttributeMaxDynamicSharedMemorySize, GSMEM_BYTES);

    // 0. round weights to tf32 (RN) into scratch
    round_tf32_kernel<<<(CD * CD + 255) / 256, 256>>>(pq_w, wpq, CD * CD);
    round_tf32_kernel<<<(CD * CD + 255) / 256, 256>>>(pk_w, wpk, CD * CD);
    round_tf32_kernel<<<(CD * CD + 255) / 256, 256>>>(pv_w, wpv, CD * CD);
    round_tf32_kernel<<<(CFF * CD + 255) / 256, 256>>>(ff1_w, wf1, CFF * CD);
    round_tf32_kernel<<<(CD * CFF + 255) / 256, 256>>>(ff2_w, wf2, CD * CFF);

    // 1. LN1
    ln1_kernel<<<CB * CN, 128>>>(x, ln1_g, ln1_b, xn);

    // 2. depthwise convs (outputs tf32-rounded)
    convq_kernel<<<dim3(CN, CB), CD>>>(xn, dwq_w, dwq_b, bnq_g, bnq_b, qc);
    convkv_kernel<<<dim3(CKV, CB), CD>>>(xn, dwk_w, dwk_b, bnk_g, bnk_b,
                                         dwv_w, dwv_b, bnv_g, bnv_b, kc, vc);

    // 3. QKV projections (mma.sync tf32)
    gemm_mma<0><<<dim3(CD / 128, CB * CN / 128), 256, GSMEM_BYTES>>>(
        qc, wpq, pq_b, nullptr, qpb, CB * CN, CD, CD);
    gemm_mma<0><<<dim3(CD / 128, CB * CKV / 128), 256, GSMEM_BYTES>>>(
        kc, wpk, pk_b, nullptr, kpb, CB * CKV, CD, CD);
    gemm_mma<0><<<dim3(CD / 128, CB * CKV / 128), 256, GSMEM_BYTES>>>(
        vc, wpv, pv_b, nullptr, vpb, CB * CKV, CD, CD);

    // 4. attention
    attn_kernel<<<dim3(CNS / 128, CH, CB), 128>>>(qpb, kpb, vpb, attnb, 0, 0, 320);
    attn_kernel<<<dim3(CNT / 128, CH, CB), 128>>>(qpb, kpb, vpb, attnb, CNS, 256, 64);

    // 5. residual + LN2 (hb tf32-rounded)
    addln2_kernel<<<CB * CN, 128>>>(x, attnb, ln2_g, ln2_b, x2b, hb);

    // 6. FFN (mma.sync tf32)
    gemm_mma<1><<<dim3(CFF / 128, CB * CN / 128), 256, GSMEM_BYTES>>>(
        hb, wf1, ff1_b, nullptr, ffb, CB * CN, CFF, CD);
    gemm_mma<2><<<dim3(CD / 128, CB * CN / 128), 256, GSMEM_BYTES>>>(
        ffb, wf2, ff2_b, x2b, out, CB * CN, CD, CFF);
}

// round 5
// speedup vs baseline: 3.2089x; 1.5178x over previous
#include <cuda_runtime.h>
#include <cuda_bf16.h>
#include <math.h>
#include <stdint.h>

// ---------------- problem constants ----------------
constexpr int CB  = 32;
constexpr int CD  = 384;
constexpr int CH  = 8;
constexpr int CHD = 48;
constexpr int CNS = 1024;
constexpr int CNT = 256;
constexpr int CN  = CNS + CNT;   // 1280
constexpr int CKV = 256 + 64;    // 320
constexpr int CFF = 4 * CD;      // 1536
constexpr float CSCALE = 0.14433756729740643f;
constexpr float EPS_LN = 1e-5f;
constexpr float EPS_BN = 1e-5f;

// ---------------- scratch ----------------
__device__ float g_xn  [(size_t)CB * CN  * CD];
__device__ float g_qc  [(size_t)CB * CN  * CD];
__device__ float g_kc  [(size_t)CB * CKV * CD];
__device__ float g_vc  [(size_t)CB * CKV * CD];
__device__ float g_qp  [(size_t)CB * CN  * CD];
__device__ float g_kp  [(size_t)CB * CKV * CD];
__device__ float g_vp  [(size_t)CB * CKV * CD];
__device__ float g_attn[(size_t)CB * CN  * CD];
__device__ float g_x2  [(size_t)CB * CN  * CD];
__device__ float g_h   [(size_t)CB * CN  * CD];
__device__ float g_ff  [(size_t)CB * CN  * CFF];
// tf32-rounded weights
__device__ float g_wpq [(size_t)CD * CD];
__device__ float g_wpk [(size_t)CD * CD];
__device__ float g_wpv [(size_t)CD * CD];
__device__ float g_wf1 [(size_t)CFF * CD];
__device__ float g_wf2 [(size_t)CD * CFF];

// ---------------- helpers ----------------
__device__ __forceinline__ float tf32r(float x) {
    uint32_t u;
    asm("cvt.rna.tf32.f32 %0, %1;" : "=r"(u) : "f"(x));
    return __uint_as_float(u);
}
__device__ __forceinline__ uint32_t smem_u32(const void* p) {
    uint32_t a;
    asm("{ .reg .u64 t; cvta.to.shared.u64 t, %1; cvt.u32.u64 %0, t; }" : "=r"(a) : "l"(p));
    return a;
}
__device__ __forceinline__ void cp_async16(uint32_t dst, const void* src) {
    asm volatile("cp.async.cg.shared.global [%0], [%1], 16;" :: "r"(dst), "l"(src) : "memory");
}
__device__ __forceinline__ void cp_commit() {
    asm volatile("cp.async.commit_group;" ::: "memory");
}
template <int N>
__device__ __forceinline__ void cp_wait() {
    asm volatile("cp.async.wait_group %0;" :: "n"(N) : "memory");
}
__device__ __forceinline__ void mma_tf32(float* c, const uint32_t* a, const uint32_t* b) {
    asm volatile(
        "mma.sync.aligned.m16n8k8.row.col.f32.tf32.tf32.f32 "
        "{%0,%1,%2,%3}, {%4,%5,%6,%7}, {%8,%9}, {%0,%1,%2,%3};"
        : "+f"(c[0]), "+f"(c[1]), "+f"(c[2]), "+f"(c[3])
        : "r"(a[0]), "r"(a[1]), "r"(a[2]), "r"(a[3]), "r"(b[0]), "r"(b[1]));
}
__device__ __forceinline__ uint32_t fau(float x) { return __float_as_uint(x); }

// round 5 weight tensors to tf32 (RN) in one launch
__global__ void round5_kernel(
    const float* s0, float* d0, int n0, const float* s1, float* d1, int n1,
    const float* s2, float* d2, int n2, const float* s3, float* d3, int n3,
    const float* s4, float* d4, int n4)
{
    int i = blockIdx.x * 256 + threadIdx.x;
    if (i < n0) { d0[i] = tf32r(s0[i]); return; } i -= n0;
    if (i < n1) { d1[i] = tf32r(s1[i]); return; } i -= n1;
    if (i < n2) { d2[i] = tf32r(s2[i]); return; } i -= n2;
    if (i < n3) { d3[i] = tf32r(s3[i]); return; } i -= n3;
    if (i < n4) { d4[i] = tf32r(s4[i]); }
}

// ---------------- mma.sync tf32 GEMM: C = A(MxK) @ W(NxK)^T + bias ----------
constexpr int GP = 36;
constexpr int GTILE = 128 * GP;
constexpr int GSMEM_BYTES = 4 * GTILE * 4;   // 73728 B

template <int EPI>   // 0 none, 1 GELU(+tf32 round), 2 +residual
__global__ __launch_bounds__(256) void gemm_mma(
    const float* __restrict__ A, const float* __restrict__ W,
    const float* __restrict__ bias, const float* __restrict__ res,
    float* __restrict__ C, int M, int NC, int K)
{
    extern __shared__ __align__(16) float smem[];
    float* As[2] = { smem,             smem + GTILE };
    float* Bs[2] = { smem + 2 * GTILE, smem + 3 * GTILE };

    const int tid  = threadIdx.x;
    const int wid  = tid >> 5;
    const int lane = tid & 31;
    const int gid  = lane >> 2;
    const int tig  = lane & 3;
    const int wr   = wid >> 2;
    const int wc   = wid & 3;

    const float* Ap = A + (size_t)blockIdx.y * 128 * K;
    const float* Wp = W + (size_t)blockIdx.x * 128 * K;

    auto load_tile = [&](int kt, int buf) {
        const uint32_t abase = smem_u32(As[buf]);
        const uint32_t bbase = smem_u32(Bs[buf]);
        #pragma unroll
        for (int i = 0; i < 4; i++) {
            const int c   = tid + i * 256;
            const int row = c >> 3;
            const int kg  = c & 7;
            const uint32_t doff = (row * GP + kg * 4) * 4;
            cp_async16(abase + doff, Ap + (size_t)row * K + kt * 32 + kg * 4);
            cp_async16(bbase + doff, Wp + (size_t)row * K + kt * 32 + kg * 4);
        }
        cp_commit();
    };

    float acc[4][4][4] = {};
    const int nk = K >> 5;
    load_tile(0, 0);

    for (int kt = 0; kt < nk; kt++) {
        const int cur = kt & 1;
        if (kt + 1 < nk) { load_tile(kt + 1, 1 - cur); cp_wait<1>(); }
        else             { cp_wait<0>(); }
        __syncthreads();

        const float* Ab = As[cur];
        const float* Bb = Bs[cur];
        #pragma unroll
        for (int ks = 0; ks < 4; ks++) {
            uint32_t af[4][4], bf[4][2];
            #pragma unroll
            for (int mi = 0; mi < 4; mi++) {
                const int r0 = wr * 64 + mi * 16 + gid;
                const int k0 = ks * 8 + tig;
                af[mi][0] = fau(Ab[r0 * GP + k0]);
                af[mi][1] = fau(Ab[(r0 + 8) * GP + k0]);
                af[mi][2] = fau(Ab[r0 * GP + k0 + 4]);
                af[mi][3] = fau(Ab[(r0 + 8) * GP + k0 + 4]);
            }
            #pragma unroll
            for (int ni = 0; ni < 4; ni++) {
                const int n0 = wc * 32 + ni * 8 + gid;
                const int k0 = ks * 8 + tig;
                bf[ni][0] = fau(Bb[n0 * GP + k0]);
                bf[ni][1] = fau(Bb[n0 * GP + k0 + 4]);
            }
            #pragma unroll
            for (int mi = 0; mi < 4; mi++)
                #pragma unroll
                for (int ni = 0; ni < 4; ni++)
                    mma_tf32(acc[mi][ni], af[mi], bf[ni]);
        }
        __syncthreads();
    }

    const int rbase = blockIdx.y * 128 + wr * 64;
    const int cbase = blockIdx.x * 128 + wc * 32;
    #pragma unroll
    for (int mi = 0; mi < 4; mi++) {
        #pragma unroll
        for (int ni = 0; ni < 4; ni++) {
            const int col = cbase + ni * 8 + 2 * tig;
            const float b0 = bias[col], b1 = bias[col + 1];
            #pragma unroll
            for (int h = 0; h < 2; h++) {
                const int row = rbase + mi * 16 + gid + h * 8;
                float v0 = acc[mi][ni][2 * h + 0] + b0;
                float v1 = acc[mi][ni][2 * h + 1] + b1;
                if (EPI == 1) {
                    v0 = 0.5f * v0 * (1.0f + erff(v0 * 0.70710678118654752f));
                    v1 = 0.5f * v1 * (1.0f + erff(v1 * 0.70710678118654752f));
                    v0 = tf32r(v0); v1 = tf32r(v1);
                }
                if (EPI == 2) {
                    const float* rp = res + (size_t)row * NC + col;
                    v0 += rp[0]; v1 += rp[1];
                }
                float2* cp = (float2*)(C + (size_t)row * NC + col);
                *cp = make_float2(v0, v1);
            }
        }
    }
}

// ---------------- flash attention via mma.sync tf32 ------------------------
// grid (numQ/128, CH, CB), 256 threads = 8 warps, warp owns 16 query rows.
// smem strides chosen conflict-free for fragment access patterns.
constexpr int AQ = 52;   // Q stride
constexpr int AK = 52;   // K stride
constexpr int AV = 56;   // V stride
constexpr int AP = 68;   // P stride
constexpr int ATT_SMEM_FLOATS = 128 * AQ + 64 * AK + 64 * AV + 128 * AP;
constexpr int ATT_SMEM_BYTES  = ATT_SMEM_FLOATS * 4;   // 89088

__global__ __launch_bounds__(256) void attn_mma_kernel(
    const float* __restrict__ qp, const float* __restrict__ kp,
    const float* __restrict__ vp, float* __restrict__ out,
    int qTokBase, int kvStart, int numKV)
{
    extern __shared__ __align__(16) float smem[];
    float* Qs = smem;                       // [128][AQ]
    float* Ks = Qs + 128 * AQ;              // [64][AK]
    float* Vs = Ks + 64 * AK;               // [64][AV]
    float* Ps = Vs + 64 * AV;               // [128][AP]

    const int b = blockIdx.z, h = blockIdx.y;
    const int qt0 = qTokBase + blockIdx.x * 128;
    const int tid = threadIdx.x, wid = tid >> 5, lane = tid & 31;
    const int gid = lane >> 2, tig = lane & 3;
    const int r0 = wid * 16;

    // load Q tile (scale + tf32 round)
    for (int idx = tid; idx < 128 * CHD; idx += 256) {
        const int r = idx / CHD, c = idx - r * CHD;
        Qs[r * AQ + c] = tf32r(qp[((size_t)b * CN + qt0 + r) * CD + h * CHD + c] * CSCALE);
    }
    __syncthreads();

    float m0 = -1e30f, m1 = -1e30f, l0 = 0.f, l1 = 0.f;
    float o[6][4] = {};

    const int nchunks = numKV >> 6;
    for (int ch = 0; ch < nchunks; ch++) {
        // cp.async K,V chunk (64 keys x 48)
        {
            const uint32_t kb = smem_u32(Ks), vb = smem_u32(Vs);
            for (int i = tid; i < 64 * 12; i += 256) {
                const int r = i / 12, c4 = i - r * 12;
                const size_t goff = ((size_t)b * CKV + kvStart + ch * 64 + r) * CD + h * CHD + c4 * 4;
                cp_async16(kb + (r * AK + c4 * 4) * 4, kp + goff);
                cp_async16(vb + (r * AV + c4 * 4) * 4, vp + goff);
            }
            cp_commit(); cp_wait<0>();
        }
        __syncthreads();

        // S = Q @ K^T : warp tile 16 x 64, k-dim 48
        float s[8][4] = {};
        #pragma unroll
        for (int ks = 0; ks < 6; ks++) {
            uint32_t af[4];
            const int k0 = ks * 8 + tig;
            af[0] = fau(Qs[(r0 + gid) * AQ + k0]);
            af[1] = fau(Qs[(r0 + gid + 8) * AQ + k0]);
            af[2] = fau(Qs[(r0 + gid) * AQ + k0 + 4]);
            af[3] = fau(Qs[(r0 + gid + 8) * AQ + k0 + 4]);
            #pragma unroll
            for (int ni = 0; ni < 8; ni++) {
                uint32_t bf[2];
                bf[0] = fau(Ks[(ni * 8 + gid) * AK + k0]);
                bf[1] = fau(Ks[(ni * 8 + gid) * AK + k0 + 4]);
                mma_tf32(s[ni], af, bf);
            }
        }

        // online softmax (rows gid -> m0/l0, gid+8 -> m1/l1)
        float mx0 = -1e30f, mx1 = -1e30f;
        #pragma unroll
        for (int ni = 0; ni < 8; ni++) {
            mx0 = fmaxf(mx0, fmaxf(s[ni][0], s[ni][1]));
            mx1 = fmaxf(mx1, fmaxf(s[ni][2], s[ni][3]));
        }
        mx0 = fmaxf(mx0, __shfl_xor_sync(0xffffffffu, mx0, 1));
        mx0 = fmaxf(mx0, __shfl_xor_sync(0xffffffffu, mx0, 2));
        mx1 = fmaxf(mx1, __shfl_xor_sync(0xffffffffu, mx1, 1));
        mx1 = fmaxf(mx1, __shfl_xor_sync(0xffffffffu, mx1, 2));
        const float m0n = fmaxf(m0, mx0), m1n = fmaxf(m1, mx1);
        const float c0 = __expf(m0 - m0n), c1 = __expf(m1 - m1n);

        float sum0 = 0.f, sum1 = 0.f;
        #pragma unroll
        for (int ni = 0; ni < 8; ni++) {
            const float p00 = __expf(s[ni][0] - m0n);
            const float p01 = __expf(s[ni][1] - m0n);
            const float p10 = __expf(s[ni][2] - m1n);
            const float p11 = __expf(s[ni][3] - m1n);
            sum0 += p00 + p01; sum1 += p10 + p11;
            const int c = ni * 8 + 2 * tig;
            *(float2*)&Ps[(r0 + gid) * AP + c]     = make_float2(p00, p01);
            *(float2*)&Ps[(r0 + gid + 8) * AP + c] = make_float2(p10, p11);
        }
        sum0 += __shfl_xor_sync(0xffffffffu, sum0, 1);
        sum0 += __shfl_xor_sync(0xffffffffu, sum0, 2);
        sum1 += __shfl_xor_sync(0xffffffffu, sum1, 1);
        sum1 += __shfl_xor_sync(0xffffffffu, sum1, 2);
        l0 = l0 * c0 + sum0;
        l1 = l1 * c1 + sum1;
        #pragma unroll
        for (int ni = 0; ni < 6; ni++) {
            o[ni][0] *= c0; o[ni][1] *= c0;
            o[ni][2] *= c1; o[ni][3] *= c1;
        }
        m0 = m0n; m1 = m1n;
        __syncwarp();

        // O += P @ V : warp tile 16 x 48, k-dim 64
        #pragma unroll
        for (int ks = 0; ks < 8; ks++) {
            uint32_t af[4];
            const int k0 = ks * 8 + tig;
            af[0] = fau(Ps[(r0 + gid) * AP + k0]);
            af[1] = fau(Ps[(r0 + gid + 8) * AP + k0]);
            af[2] = fau(Ps[(r0 + gid) * AP + k0 + 4]);
            af[3] = fau(Ps[(r0 + gid + 8) * AP + k0 + 4]);
            #pragma unroll
            for (int ni = 0; ni < 6; ni++) {
                uint32_t bf[2];
                bf[0] = fau(Vs[k0 * AV + ni * 8 + gid]);
                bf[1] = fau(Vs[(k0 + 4) * AV + ni * 8 + gid]);
                mma_tf32(o[ni], af, bf);
            }
        }
        __syncthreads();   // protect Ks/Vs before next chunk's cp.async
    }

    // epilogue
    const float inv0 = 1.0f / l0, inv1 = 1.0f / l1;
    #pragma unroll
    for (int ni = 0; ni < 6; ni++) {
        const int col = h * CHD + ni * 8 + 2 * tig;
        const int row0 = qt0 + r0 + gid;
        *(float2*)&out[((size_t)b * CN + row0) * CD + col] =
            make_float2(o[ni][0] * inv0, o[ni][1] * inv0);
        *(float2*)&out[((size_t)b * CN + row0 + 8) * CD + col] =
            make_float2(o[ni][2] * inv1, o[ni][3] * inv1);
    }
}

// ---------------- LayerNorm 1 ----------------
__global__ __launch_bounds__(128) void ln1_kernel(
    const float* __restrict__ x, const float* __restrict__ g,
    const float* __restrict__ b, float* __restrict__ out)
{
    const size_t tok = blockIdx.x;
    const int tid = threadIdx.x;
    const float* xp = x + tok * CD;

    float v0 = xp[tid], v1 = xp[tid + 128], v2 = xp[tid + 256];
    float s = v0 + v1 + v2;
    float q = v0 * v0 + v1 * v1 + v2 * v2;
    #pragma unroll
    for (int o = 16; o > 0; o >>= 1) {
        s += __shfl_xor_sync(0xffffffffu, s, o);
        q += __shfl_xor_sync(0xffffffffu, q, o);
    }
    __shared__ float ss[4], sq[4];
    if ((tid & 31) == 0) { ss[tid >> 5] = s; sq[tid >> 5] = q; }
    __syncthreads();
    s = ss[0] + ss[1] + ss[2] + ss[3];
    q = sq[0] + sq[1] + sq[2] + sq[3];
    const float mean = s * (1.0f / CD);
    const float var  = q * (1.0f / CD) - mean * mean;
    const float inv  = rsqrtf(var + EPS_LN);

    float* op = out + tok * CD;
    op[tid]       = (v0 - mean) * inv * g[tid]       + b[tid];
    op[tid + 128] = (v1 - mean) * inv * g[tid + 128] + b[tid + 128];
    op[tid + 256] = (v2 - mean) * inv * g[tid + 256] + b[tid + 256];
}

// --------- residual add + LayerNorm 2 (ln output tf32-rounded for FF1) -----
__global__ __launch_bounds__(128) void addln2_kernel(
    const float* __restrict__ x, const float* __restrict__ attn,
    const float* __restrict__ g, const float* __restrict__ b,
    float* __restrict__ x2, float* __restrict__ out)
{
    const size_t tok = blockIdx.x;
    const int tid = threadIdx.x;
    const float* xp = x    + tok * CD;
    const float* ap = attn + tok * CD;

    float v0 = xp[tid]       + ap[tid];
    float v1 = xp[tid + 128] + ap[tid + 128];
    float v2 = xp[tid + 256] + ap[tid + 256];
    float* x2p = x2 + tok * CD;
    x2p[tid] = v0; x2p[tid + 128] = v1; x2p[tid + 256] = v2;

    float s = v0 + v1 + v2;
    float q = v0 * v0 + v1 * v1 + v2 * v2;
    #pragma unroll
    for (int o = 16; o > 0; o >>= 1) {
        s += __shfl_xor_sync(0xffffffffu, s, o);
        q += __shfl_xor_sync(0xffffffffu, q, o);
    }
    __shared__ float ss[4], sq[4];
    if ((tid & 31) == 0) { ss[tid >> 5] = s; sq[tid >> 5] = q; }
    __syncthreads();
    s = ss[0] + ss[1] + ss[2] + ss[3];
    q = sq[0] + sq[1] + sq[2] + sq[3];
    const float mean = s * (1.0f / CD);
    const float var  = q * (1.0f / CD) - mean * mean;
    const float inv  = rsqrtf(var + EPS_LN);

    float* op = out + tok * CD;
    op[tid]       = tf32r((v0 - mean) * inv * g[tid]       + b[tid]);
    op[tid + 128] = tf32r((v1 - mean) * inv * g[tid + 128] + b[tid + 128]);
    op[tid + 256] = tf32r((v2 - mean) * inv * g[tid + 256] + b[tid + 256]);
}

// ----- depthwise 3x3 conv stride 1 pad 1 (Q path), output tf32-rounded -----
__global__ __launch_bounds__(CD) void convq_kernel(
    const float* __restrict__ xn, const float* __restrict__ w,
    const float* __restrict__ cb, const float* __restrict__ bg,
    const float* __restrict__ bb, float* __restrict__ out)
{
    const int t = blockIdx.x, bidx = blockIdx.y, d = threadIdx.x;
    int hw, loc, base;
    if (t < CNS) { hw = 32; loc = t;        base = 0;   }
    else         { hw = 16; loc = t - CNS;  base = CNS; }
    const int oy = loc / hw, ox = loc % hw;

    float s = 0.f;
    #pragma unroll
    for (int ky = 0; ky < 3; ky++) {
        const int iy = oy + ky - 1;
        if ((unsigned)iy >= (unsigned)hw) continue;
        #pragma unroll
        for (int kx = 0; kx < 3; kx++) {
            const int ix = ox + kx - 1;
            if ((unsigned)ix >= (unsigned)hw) continue;
            s += w[d * 9 + ky * 3 + kx] *
                 xn[((size_t)bidx * CN + base + iy * hw + ix) * CD + d];
        }
    }
    const float sc = bg[d] * rsqrtf(1.0f + EPS_BN);
    out[((size_t)bidx * CN + t) * CD + d] = tf32r((s + cb[d]) * sc + bb[d]);
}

// ----- depthwise 3x3 conv stride 2 pad 1, K & V, outputs tf32-rounded ------
__global__ __launch_bounds__(CD) void convkv_kernel(
    const float* __restrict__ xn,
    const float* __restrict__ wk, const float* __restrict__ cbk,
    const float* __restrict__ bgk, const float* __restrict__ bbk,
    const float* __restrict__ wv, const float* __restrict__ cbv,
    const float* __restrict__ bgv, const float* __restrict__ bbv,
    float* __restrict__ outk, float* __restrict__ outv)
{
    const int t = blockIdx.x, bidx = blockIdx.y, d = threadIdx.x;
    int hwin, hwout, loc, base;
    if (t < 256) { hwin = 32; hwout = 16; loc = t;       base = 0;   }
    else         { hwin = 16; hwout = 8;  loc = t - 256; base = CNS; }
    const int oy = loc / hwout, ox = loc % hwout;

    float sk = 0.f, sv = 0.f;
    #pragma unroll
    for (int ky = 0; ky < 3; ky++) {
        const int iy = 2 * oy + ky - 1;
        if ((unsigned)iy >= (unsigned)hwin) continue;
        #pragma unroll
        for (int kx = 0; kx < 3; kx++) {
            const int ix = 2 * ox + kx - 1;
            if ((unsigned)ix >= (unsigned)hwin) continue;
            const float xv = xn[((size_t)bidx * CN + base + iy * hwin + ix) * CD + d];
            sk += wk[d * 9 + ky * 3 + kx] * xv;
            sv += wv[d * 9 + ky * 3 + kx] * xv;
        }
    }
    const size_t o = ((size_t)bidx * CKV + t) * CD + d;
    outk[o] = tf32r((sk + cbk[d]) * (bgk[d] * rsqrtf(1.0f + EPS_BN)) + bbk[d]);
    outv[o] = tf32r((sv + cbv[d]) * (bgv[d] * rsqrtf(1.0f + EPS_BN)) + bbv[d]);
}

// ---------------- launch ----------------
extern "C" void kernel_launch(void* const* d_in, const int* in_sizes, int n_in,
                              void* d_out, int out_size)
{
    const float* x     = (const float*)d_in[0];
    const float* ln1_g = (const float*)d_in[1];
    const float* ln1_b = (const float*)d_in[2];
    const float* dwq_w = (const float*)d_in[3];
    const float* dwq_b = (const float*)d_in[4];
    const float* bnq_g = (const float*)d_in[5];
    const float* bnq_b = (const float*)d_in[6];
    const float* dwk_w = (const float*)d_in[7];
    const float* dwk_b = (const float*)d_in[8];
    const float* bnk_g = (const float*)d_in[9];
    const float* bnk_b = (const float*)d_in[10];
    const float* dwv_w = (const float*)d_in[11];
    const float* dwv_b = (const float*)d_in[12];
    const float* bnv_g = (const float*)d_in[13];
    const float* bnv_b = (const float*)d_in[14];
    const float* pq_w  = (const float*)d_in[15];
    const float* pq_b  = (const float*)d_in[16];
    const float* pk_w  = (const float*)d_in[17];
    const float* pk_b  = (const float*)d_in[18];
    const float* pv_w  = (const float*)d_in[19];
    const float* pv_b  = (const float*)d_in[20];
    const float* ln2_g = (const float*)d_in[21];
    const float* ln2_b = (const float*)d_in[22];
    const float* ff1_w = (const float*)d_in[23];
    const float* ff1_b = (const float*)d_in[24];
    const float* ff2_w = (const float*)d_in[25];
    const float* ff2_b = (const float*)d_in[26];
    float* out = (float*)d_out;

    float *xn, *qc, *kc, *vc, *qpb, *kpb, *vpb, *attnb, *x2b, *hb, *ffb;
    float *wpq, *wpk, *wpv, *wf1, *wf2;
    cudaGetSymbolAddress((void**)&xn,    g_xn);
    cudaGetSymbolAddress((void**)&qc,    g_qc);
    cudaGetSymbolAddress((void**)&kc,    g_kc);
    cudaGetSymbolAddress((void**)&vc,    g_vc);
    cudaGetSymbolAddress((void**)&qpb,   g_qp);
    cudaGetSymbolAddress((void**)&kpb,   g_kp);
    cudaGetSymbolAddress((void**)&vpb,   g_vp);
    cudaGetSymbolAddress((void**)&attnb, g_attn);
    cudaGetSymbolAddress((void**)&x2b,   g_x2);
    cudaGetSymbolAddress((void**)&hb,    g_h);
    cudaGetSymbolAddress((void**)&ffb,   g_ff);
    cudaGetSymbolAddress((void**)&wpq,   g_wpq);
    cudaGetSymbolAddress((void**)&wpk,   g_wpk);
    cudaGetSymbolAddress((void**)&wpv,   g_wpv);
    cudaGetSymbolAddress((void**)&wf1,   g_wf1);
    cudaGetSymbolAddress((void**)&wf2,   g_wf2);

    cudaFuncSetAttribute(gemm_mma<0>, cudaFuncAttributeMaxDynamicSharedMemorySize, GSMEM_BYTES);
    cudaFuncSetAttribute(gemm_mma<1>, cudaFuncAttributeMaxDynamicSharedMemorySize, GSMEM_BYTES);
    cudaFuncSetAttribute(gemm_mma<2>, cudaFuncAttributeMaxDynamicSharedMemorySize, GSMEM_BYTES);
    cudaFuncSetAttribute(attn_mma_kernel, cudaFuncAttributeMaxDynamicSharedMemorySize, ATT_SMEM_BYTES);

    // 0. round weights to tf32 (one launch)
    {
        const int n01 = CD * CD, n3 = CFF * CD, n4 = CD * CFF;
        const int total = 3 * n01 + n3 + n4;
        round5_kernel<<<(total + 255) / 256, 256>>>(
            pq_w, wpq, n01, pk_w, wpk, n01, pv_w, wpv, n01,
            ff1_w, wf1, n3, ff2_w, wf2, n4);
    }

    // 1. LN1
    ln1_kernel<<<CB * CN, 128>>>(x, ln1_g, ln1_b, xn);

    // 2. depthwise convs (outputs tf32-rounded)
    convq_kernel<<<dim3(CN, CB), CD>>>(xn, dwq_w, dwq_b, bnq_g, bnq_b, qc);
    convkv_kernel<<<dim3(CKV, CB), CD>>>(xn, dwk_w, dwk_b, bnk_g, bnk_b,
                                         dwv_w, dwv_b, bnv_g, bnv_b, kc, vc);

    // 3. QKV projections (mma.sync tf32)
    gemm_mma<0><<<dim3(CD / 128, CB * CN / 128), 256, GSMEM_BYTES>>>(
        qc, wpq, pq_b, nullptr, qpb, CB * CN, CD, CD);
    gemm_mma<0><<<dim3(CD / 128, CB * CKV / 128), 256, GSMEM_BYTES>>>(
        kc, wpk, pk_b, nullptr, kpb, CB * CKV, CD, CD);
    gemm_mma<0><<<dim3(CD / 128, CB * CKV / 128), 256, GSMEM_BYTES>>>(
        vc, wpv, pv_b, nullptr, vpb, CB * CKV, CD, CD);

    // 4. flash attention (mma.sync tf32)
    attn_mma_kernel<<<dim3(CNS / 128, CH, CB), 256, ATT_SMEM_BYTES>>>(
        qpb, kpb, vpb, attnb, 0, 0, 320);
    attn_mma_kernel<<<dim3(CNT / 128, CH, CB), 256, ATT_SMEM_BYTES>>>(
        qpb, kpb, vpb, attnb, CNS, 256, 64);

    // 5. residual + LN2
    addln2_kernel<<<CB * CN, 128>>>(x, attnb, ln2_g, ln2_b, x2b, hb);

    // 6. FFN (mma.sync tf32)
    gemm_mma<1><<<dim3(CFF / 128, CB * CN / 128), 256, GSMEM_BYTES>>>(
        hb, wf1, ff1_b, nullptr, ffb, CB * CN, CFF, CD);
    gemm_mma<2><<<dim3(CD / 128, CB * CN / 128), 256, GSMEM_BYTES>>>(
        ffb, wf2, ff2_b, x2b, out, CB * CN, CD, CFF);
}

// round 8
// speedup vs baseline: 3.2429x; 1.0106x over previous
#include <cuda_runtime.h>
#include <cuda_bf16.h>
#include <math.h>
#include <stdint.h>

// ---------------- problem constants ----------------
constexpr int CB  = 32;
constexpr int CD  = 384;
constexpr int CH  = 8;
constexpr int CHD = 48;
constexpr int CNS = 1024;
constexpr int CNT = 256;
constexpr int CN  = CNS + CNT;   // 1280
constexpr int CKV = 256 + 64;    // 320
constexpr int CFF = 4 * CD;      // 1536
constexpr float CSCALE = 0.14433756729740643f;
constexpr float EPS_LN = 1e-5f;
constexpr float EPS_BN = 1e-5f;

// ---------------- scratch ----------------
__device__ float g_xn  [(size_t)CB * CN  * CD];
__device__ float g_qc  [(size_t)CB * CN  * CD];
__device__ float g_kc  [(size_t)CB * CKV * CD];
__device__ float g_vc  [(size_t)CB * CKV * CD];
__device__ float g_qp  [(size_t)CB * CN  * CD];
__device__ float g_kp  [(size_t)CB * CKV * CD];
__device__ float g_vp  [(size_t)CB * CKV * CD];
__device__ float g_attn[(size_t)CB * CN  * CD];
__device__ float g_x2  [(size_t)CB * CN  * CD];
__device__ float g_h   [(size_t)CB * CN  * CD];
__device__ float g_ff  [(size_t)CB * CN  * CFF];
__device__ float g_wpq [(size_t)CD * CD];
__device__ float g_wpk [(size_t)CD * CD];
__device__ float g_wpv [(size_t)CD * CD];
__device__ float g_wf1 [(size_t)CFF * CD];
__device__ float g_wf2 [(size_t)CD * CFF];

// ---------------- helpers ----------------
__device__ __forceinline__ float tf32r(float x) {
    uint32_t u;
    asm("cvt.rna.tf32.f32 %0, %1;" : "=r"(u) : "f"(x));
    return __uint_as_float(u);
}
__device__ __forceinline__ uint32_t smem_u32(const void* p) {
    uint32_t a;
    asm("{ .reg .u64 t; cvta.to.shared.u64 t, %1; cvt.u32.u64 %0, t; }" : "=r"(a) : "l"(p));
    return a;
}
__device__ __forceinline__ void cp_async16(uint32_t dst, const void* src) {
    asm volatile("cp.async.cg.shared.global [%0], [%1], 16;" :: "r"(dst), "l"(src) : "memory");
}
__device__ __forceinline__ void cp_commit() {
    asm volatile("cp.async.commit_group;" ::: "memory");
}
template <int N>
__device__ __forceinline__ void cp_wait() {
    asm volatile("cp.async.wait_group %0;" :: "n"(N) : "memory");
}
__device__ __forceinline__ void mma_tf32(float* c, const uint32_t* a, const uint32_t* b) {
    asm volatile(
        "mma.sync.aligned.m16n8k8.row.col.f32.tf32.tf32.f32 "
        "{%0,%1,%2,%3}, {%4,%5,%6,%7}, {%8,%9}, {%0,%1,%2,%3};"
        : "+f"(c[0]), "+f"(c[1]), "+f"(c[2]), "+f"(c[3])
        : "r"(a[0]), "r"(a[1]), "r"(a[2]), "r"(a[3]), "r"(b[0]), "r"(b[1]));
}
__device__ __forceinline__ uint32_t fau(float x) { return __float_as_uint(x); }

// round 5 weight tensors to tf32 (RN) in one launch
__global__ void round5_kernel(
    const float* s0, float* d0, int n0, const float* s1, float* d1, int n1,
    const float* s2, float* d2, int n2, const float* s3, float* d3, int n3,
    const float* s4, float* d4, int n4)
{
    int i = blockIdx.x * 256 + threadIdx.x;
    if (i < n0) { d0[i] = tf32r(s0[i]); return; } i -= n0;
    if (i < n1) { d1[i] = tf32r(s1[i]); return; } i -= n1;
    if (i < n2) { d2[i] = tf32r(s2[i]); return; } i -= n2;
    if (i < n3) { d3[i] = tf32r(s3[i]); return; } i -= n3;
    if (i < n4) { d4[i] = tf32r(s4[i]); }
}

// ---------------- mma.sync tf32 GEMM core (proven 2-stage pipeline) --------
// Tile 128x128x32, 256 threads = 8 warps (2x4), warp tile 64x32.
constexpr int GP    = 36;
constexpr int GTILE = 128 * GP;
constexpr int GSMEM_BYTES = 4 * GTILE * 4;   // A0,A1,B0,B1 = 73728 B

template <int EPI>   // 0 none, 1 GELU(+tf32 round), 2 +residual
__device__ __forceinline__ void gemm_core(
    const float* __restrict__ Ap, const float* __restrict__ Wp,
    const float* __restrict__ biasp, const float* __restrict__ resp,
    float* __restrict__ Cp, int ldc, int K)
{
    extern __shared__ __align__(16) float smem[];
    float* As[2] = { smem,             smem + GTILE };
    float* Bs[2] = { smem + 2 * GTILE, smem + 3 * GTILE };

    const int tid  = threadIdx.x;
    const int wid  = tid >> 5;
    const int lane = tid & 31;
    const int gid  = lane >> 2;
    const int tig  = lane & 3;
    const int wr   = wid >> 2;
    const int wc   = wid & 3;

    auto load_tile = [&](int kt, int buf) {
        const uint32_t abase = smem_u32(As[buf]);
        const uint32_t bbase = smem_u32(Bs[buf]);
        #pragma unroll
        for (int i = 0; i < 4; i++) {
            const int c   = tid + i * 256;
            const int row = c >> 3;
            const int kg  = c & 7;
            const uint32_t doff = (row * GP + kg * 4) * 4;
            cp_async16(abase + doff, Ap + (size_t)row * K + kt * 32 + kg * 4);
            cp_async16(bbase + doff, Wp + (size_t)row * K + kt * 32 + kg * 4);
        }
        cp_commit();
    };

    float acc[4][4][4] = {};
    const int nk = K >> 5;
    load_tile(0, 0);

    for (int kt = 0; kt < nk; kt++) {
        const int cur = kt & 1;
        if (kt + 1 < nk) { load_tile(kt + 1, 1 - cur); cp_wait<1>(); }
        else             { cp_wait<0>(); }
        __syncthreads();

        const float* Ab = As[cur];
        const float* Bb = Bs[cur];
        #pragma unroll
        for (int ks = 0; ks < 4; ks++) {
            uint32_t af[4][4], bf[4][2];
            #pragma unroll
            for (int mi = 0; mi < 4; mi++) {
                const int r0 = wr * 64 + mi * 16 + gid;
                const int k0 = ks * 8 + tig;
                af[mi][0] = fau(Ab[r0 * GP + k0]);
                af[mi][1] = fau(Ab[(r0 + 8) * GP + k0]);
                af[mi][2] = fau(Ab[r0 * GP + k0 + 4]);
                af[mi][3] = fau(Ab[(r0 + 8) * GP + k0 + 4]);
            }
            #pragma unroll
            for (int ni = 0; ni < 4; ni++) {
                const int n0 = wc * 32 + ni * 8 + gid;
                const int k0 = ks * 8 + tig;
                bf[ni][0] = fau(Bb[n0 * GP + k0]);
                bf[ni][1] = fau(Bb[n0 * GP + k0 + 4]);
            }
            #pragma unroll
            for (int mi = 0; mi < 4; mi++)
                #pragma unroll
                for (int ni = 0; ni < 4; ni++)
                    mma_tf32(acc[mi][ni], af[mi], bf[ni]);
        }
        __syncthreads();
    }

    #pragma unroll
    for (int mi = 0; mi < 4; mi++) {
        #pragma unroll
        for (int ni = 0; ni < 4; ni++) {
            const int col = wc * 32 + ni * 8 + 2 * tig;
            const float b0 = biasp[col], b1 = biasp[col + 1];
            #pragma unroll
            for (int h = 0; h < 2; h++) {
                const int row = wr * 64 + mi * 16 + gid + h * 8;
                float v0 = acc[mi][ni][2 * h + 0] + b0;
                float v1 = acc[mi][ni][2 * h + 1] + b1;
                if (EPI == 1) {
                    v0 = 0.5f * v0 * (1.0f + erff(v0 * 0.70710678118654752f));
                    v1 = 0.5f * v1 * (1.0f + erff(v1 * 0.70710678118654752f));
                    v0 = tf32r(v0); v1 = tf32r(v1);
                }
                if (EPI == 2) {
                    const float* rp = resp + (size_t)row * ldc + col;
                    v0 += rp[0]; v1 += rp[1];
                }
                *(float2*)(Cp + (size_t)row * ldc + col) = make_float2(v0, v1);
            }
        }
    }
}

// fused Q/K/V projection: grid (3, 480). y<320: Q rows, 320..400: K, 400..480: V
__global__ __launch_bounds__(256) void qkv_kernel(
    const float* __restrict__ qc, const float* __restrict__ kc, const float* __restrict__ vc,
    const float* __restrict__ wq, const float* __restrict__ wk, const float* __restrict__ wv,
    const float* __restrict__ bq, const float* __restrict__ bk, const float* __restrict__ bv,
    float* __restrict__ qp, float* __restrict__ kp, float* __restrict__ vp)
{
    int y = blockIdx.y;
    const float *A, *W, *bias;
    float* C;
    if (y < 320)      { A = qc; W = wq; bias = bq; C = qp; }
    else if (y < 400) { y -= 320; A = kc; W = wk; bias = bk; C = kp; }
    else              { y -= 400; A = vc; W = wv; bias = bv; C = vp; }
    const int bx = blockIdx.x;
    gemm_core<0>(A + (size_t)y * 128 * CD, W + (size_t)bx * 128 * CD,
                 bias + bx * 128, nullptr,
                 C + (size_t)y * 128 * CD + bx * 128, CD, CD);
}

template <int EPI>
__global__ __launch_bounds__(256) void gemm_mma(
    const float* __restrict__ A, const float* __restrict__ W,
    const float* __restrict__ bias, const float* __restrict__ res,
    float* __restrict__ C, int NC, int K)
{
    const int bx = blockIdx.x, by = blockIdx.y;
    gemm_core<EPI>(A + (size_t)by * 128 * K, W + (size_t)bx * 128 * K,
                   bias + bx * 128,
                   (EPI == 2) ? (res + (size_t)by * 128 * NC + bx * 128) : nullptr,
                   C + (size_t)by * 128 * NC + bx * 128, NC, K);
}

// ---------------- flash attention via mma.sync tf32 ------------------------
// grid (10, CH, CB): x<8 -> search q-block x (kv 0..320); x>=8 -> target (kv 256..320)
constexpr int AQ = 52;
constexpr int AK = 52;
constexpr int AV = 56;
constexpr int AP = 68;
constexpr int ATT_SMEM_FLOATS = 128 * AQ + 64 * AK + 64 * AV + 128 * AP;
constexpr int ATT_SMEM_BYTES  = ATT_SMEM_FLOATS * 4;   // 89088

__global__ __launch_bounds__(256) void attn_mma_kernel(
    const float* __restrict__ qp, const float* __restrict__ kp,
    const float* __restrict__ vp, float* __restrict__ out)
{
    extern __shared__ __align__(16) float smem[];
    float* Qs = smem;
    float* Ks = Qs + 128 * AQ;
    float* Vs = Ks + 64 * AK;
    float* Ps = Vs + 64 * AV;

    const int b = blockIdx.z, h = blockIdx.y;
    int qt0, kvStart, numKV;
    if (blockIdx.x < 8) { qt0 = blockIdx.x * 128;              kvStart = 0;   numKV = 320; }
    else                { qt0 = CNS + (blockIdx.x - 8) * 128;  kvStart = 256; numKV = 64;  }

    const int tid = threadIdx.x, wid = tid >> 5, lane = tid & 31;
    const int gid = lane >> 2, tig = lane & 3;
    const int r0 = wid * 16;

    for (int idx = tid; idx < 128 * CHD; idx += 256) {
        const int r = idx / CHD, c = idx - r * CHD;
        Qs[r * AQ + c] = tf32r(qp[((size_t)b * CN + qt0 + r) * CD + h * CHD + c] * CSCALE);
    }
    __syncthreads();

    float m0 = -1e30f, m1 = -1e30f, l0 = 0.f, l1 = 0.f;
    float o[6][4] = {};

    const int nchunks = numKV >> 6;
    for (int ch = 0; ch < nchunks; ch++) {
        {
            const uint32_t kb = smem_u32(Ks), vb = smem_u32(Vs);
            for (int i = tid; i < 64 * 12; i += 256) {
                const int r = i / 12, c4 = i - r * 12;
                const size_t goff = ((size_t)b * CKV + kvStart + ch * 64 + r) * CD + h * CHD + c4 * 4;
                cp_async16(kb + (r * AK + c4 * 4) * 4, kp + goff);
                cp_async16(vb + (r * AV + c4 * 4) * 4, vp + goff);
            }
            cp_commit(); cp_wait<0>();
        }
        __syncthreads();

        float s[8][4] = {};
        #pragma unroll
        for (int ks = 0; ks < 6; ks++) {
            uint32_t af[4];
            const int k0 = ks * 8 + tig;
            af[0] = fau(Qs[(r0 + gid) * AQ + k0]);
            af[1] = fau(Qs[(r0 + gid + 8) * AQ + k0]);
            af[2] = fau(Qs[(r0 + gid) * AQ + k0 + 4]);
            af[3] = fau(Qs[(r0 + gid + 8) * AQ + k0 + 4]);
            #pragma unroll
            for (int ni = 0; ni < 8; ni++) {
                uint32_t bf[2];
                bf[0] = fau(Ks[(ni * 8 + gid) * AK + k0]);
                bf[1] = fau(Ks[(ni * 8 + gid) * AK + k0 + 4]);
                mma_tf32(s[ni], af, bf);
            }
        }

        float mx0 = -1e30f, mx1 = -1e30f;
        #pragma unroll
        for (int ni = 0; ni < 8; ni++) {
            mx0 = fmaxf(mx0, fmaxf(s[ni][0], s[ni][1]));
            mx1 = fmaxf(mx1, fmaxf(s[ni][2], s[ni][3]));
        }
        mx0 = fmaxf(mx0, __shfl_xor_sync(0xffffffffu, mx0, 1));
        mx0 = fmaxf(mx0, __shfl_xor_sync(0xffffffffu, mx0, 2));
        mx1 = fmaxf(mx1, __shfl_xor_sync(0xffffffffu, mx1, 1));
        mx1 = fmaxf(mx1, __shfl_xor_sync(0xffffffffu, mx1, 2));
        const float m0n = fmaxf(m0, mx0), m1n = fmaxf(m1, mx1);
        const float c0 = __expf(m0 - m0n), c1 = __expf(m1 - m1n);

        float sum0 = 0.f, sum1 = 0.f;
        #pragma unroll
        for (int ni = 0; ni < 8; ni++) {
            const float p00 = __expf(s[ni][0] - m0n);
            const float p01 = __expf(s[ni][1] - m0n);
            const float p10 = __expf(s[ni][2] - m1n);
            const float p11 = __expf(s[ni][3] - m1n);
            sum0 += p00 + p01; sum1 += p10 + p11;
            const int c = ni * 8 + 2 * tig;
            *(float2*)&Ps[(r0 + gid) * AP + c]     = make_float2(p00, p01);
            *(float2*)&Ps[(r0 + gid + 8) * AP + c] = make_float2(p10, p11);
        }
        sum0 += __shfl_xor_sync(0xffffffffu, sum0, 1);
        sum0 += __shfl_xor_sync(0xffffffffu, sum0, 2);
        sum1 += __shfl_xor_sync(0xffffffffu, sum1, 1);
        sum1 += __shfl_xor_sync(0xffffffffu, sum1, 2);
        l0 = l0 * c0 + sum0;
        l1 = l1 * c1 + sum1;
        #pragma unroll
        for (int ni = 0; ni < 6; ni++) {
            o[ni][0] *= c0; o[ni][1] *= c0;
            o[ni][2] *= c1; o[ni][3] *= c1;
        }
        m0 = m0n; m1 = m1n;
        __syncwarp();

        #pragma unroll
        for (int ks = 0; ks < 8; ks++) {
            uint32_t af[4];
            const int k0 = ks * 8 + tig;
            af[0] = fau(Ps[(r0 + gid) * AP + k0]);
            af[1] = fau(Ps[(r0 + gid + 8) * AP + k0]);
            af[2] = fau(Ps[(r0 + gid) * AP + k0 + 4]);
            af[3] = fau(Ps[(r0 + gid + 8) * AP + k0 + 4]);
            #pragma unroll
            for (int ni = 0; ni < 6; ni++) {
                uint32_t bf[2];
                bf[0] = fau(Vs[k0 * AV + ni * 8 + gid]);
                bf[1] = fau(Vs[(k0 + 4) * AV + ni * 8 + gid]);
                mma_tf32(o[ni], af, bf);
            }
        }
        __syncthreads();
    }

    const float inv0 = 1.0f / l0, inv1 = 1.0f / l1;
    #pragma unroll
    for (int ni = 0; ni < 6; ni++) {
        const int col = h * CHD + ni * 8 + 2 * tig;
        const int row0 = qt0 + r0 + gid;
        *(float2*)&out[((size_t)b * CN + row0) * CD + col] =
            make_float2(o[ni][0] * inv0, o[ni][1] * inv0);
        *(float2*)&out[((size_t)b * CN + row0 + 8) * CD + col] =
            make_float2(o[ni][2] * inv1, o[ni][3] * inv1);
    }
}

// ---------------- LayerNorm 1 ----------------
__global__ __launch_bounds__(128) void ln1_kernel(
    const float* __restrict__ x, const float* __restrict__ g,
    const float* __restrict__ b, float* __restrict__ out)
{
    const size_t tok = blockIdx.x;
    const int tid = threadIdx.x;
    const float* xp = x + tok * CD;

    float v0 = xp[tid], v1 = xp[tid + 128], v2 = xp[tid + 256];
    float s = v0 + v1 + v2;
    float q = v0 * v0 + v1 * v1 + v2 * v2;
    #pragma unroll
    for (int o = 16; o > 0; o >>= 1) {
        s += __shfl_xor_sync(0xffffffffu, s, o);
        q += __shfl_xor_sync(0xffffffffu, q, o);
    }
    __shared__ float ss[4], sq[4];
    if ((tid & 31) == 0) { ss[tid >> 5] = s; sq[tid >> 5] = q; }
    __syncthreads();
    s = ss[0] + ss[1] + ss[2] + ss[3];
    q = sq[0] + sq[1] + sq[2] + sq[3];
    const float mean = s * (1.0f / CD);
    const float var  = q * (1.0f / CD) - mean * mean;
    const float inv  = rsqrtf(var + EPS_LN);

    float* op = out + tok * CD;
    op[tid]       = (v0 - mean) * inv * g[tid]       + b[tid];
    op[tid + 128] = (v1 - mean) * inv * g[tid + 128] + b[tid + 128];
    op[tid + 256] = (v2 - mean) * inv * g[tid + 256] + b[tid + 256];
}

// --------- residual add + LayerNorm 2 (ln output tf32-rounded for FF1) -----
__global__ __launch_bounds__(128) void addln2_kernel(
    const float* __restrict__ x, const float* __restrict__ attn,
    const float* __restrict__ g, const float* __restrict__ b,
    float* __restrict__ x2, float* __restrict__ out)
{
    const size_t tok = blockIdx.x;
    const int tid = threadIdx.x;
    const float* xp = x    + tok * CD;
    const float* ap = attn + tok * CD;

    float v0 = xp[tid]       + ap[tid];
    float v1 = xp[tid + 128] + ap[tid + 128];
    float v2 = xp[tid + 256] + ap[tid + 256];
    float* x2p = x2 + tok * CD;
    x2p[tid] = v0; x2p[tid + 128] = v1; x2p[tid + 256] = v2;

    float s = v0 + v1 + v2;
    float q = v0 * v0 + v1 * v1 + v2 * v2;
    #pragma unroll
    for (int o = 16; o > 0; o >>= 1) {
        s += __shfl_xor_sync(0xffffffffu, s, o);
        q += __shfl_xor_sync(0xffffffffu, q, o);
    }
    __shared__ float ss[4], sq[4];
    if ((tid & 31) == 0) { ss[tid >> 5] = s; sq[tid >> 5] = q; }
    __syncthreads();
    s = ss[0] + ss[1] + ss[2] + ss[3];
    q = sq[0] + sq[1] + sq[2] + sq[3];
    const float mean = s * (1.0f / CD);
    const float var  = q * (1.0f / CD) - mean * mean;
    const float inv  = rsqrtf(var + EPS_LN);

    float* op = out + tok * CD;
    op[tid]       = tf32r((v0 - mean) * inv * g[tid]       + b[tid]);
    op[tid + 128] = tf32r((v1 - mean) * inv * g[tid + 128] + b[tid + 128]);
    op[tid + 256] = tf32r((v2 - mean) * inv * g[tid + 256] + b[tid + 256]);
}

// ----- depthwise 3x3 conv stride 1 pad 1 (Q path), 4 tokens per block ------
__global__ __launch_bounds__(CD) void convq_kernel(
    const float* __restrict__ xn, const float* __restrict__ w,
    const float* __restrict__ cb, const float* __restrict__ bg,
    const float* __restrict__ bb, float* __restrict__ out)
{
    const int t0 = blockIdx.x * 4, bidx = blockIdx.y, d = threadIdx.x;
    float w9[9];
    #pragma unroll
    for (int i = 0; i < 9; i++) w9[i] = w[d * 9 + i];
    const float sc  = bg[d] * rsqrtf(1.0f + EPS_BN);
    const float cbd = cb[d], bbd = bb[d];

    #pragma unroll
    for (int ti = 0; ti < 4; ti++) {
        const int t = t0 + ti;
        int hw, loc, base;
        if (t < CNS) { hw = 32; loc = t;        base = 0;   }
        else         { hw = 16; loc = t - CNS;  base = CNS; }
        const int oy = loc / hw, ox = loc % hw;

        float s = 0.f;
        #pragma unroll
        for (int ky = 0; ky < 3; ky++) {
            const int iy = oy + ky - 1;
            if ((unsigned)iy >= (unsigned)hw) continue;
            #pragma unroll
            for (int kx = 0; kx < 3; kx++) {
                const int ix = ox + kx - 1;
                if ((unsigned)ix >= (unsigned)hw) continue;
                s += w9[ky * 3 + kx] *
                     xn[((size_t)bidx * CN + base + iy * hw + ix) * CD + d];
            }
        }
        out[((size_t)bidx * CN + t) * CD + d] = tf32r((s + cbd) * sc + bbd);
    }
}

// ----- depthwise 3x3 conv stride 2 pad 1, K & V, 4 tokens per block --------
__global__ __launch_bounds__(CD) void convkv_kernel(
    const float* __restrict__ xn,
    const float* __restrict__ wk, const float* __restrict__ cbk,
    const float* __restrict__ bgk, const float* __restrict__ bbk,
    const float* __restrict__ wv, const float* __restrict__ cbv,
    const float* __restrict__ bgv, const float* __restrict__ bbv,
    float* __restrict__ outk, float* __restrict__ outv)
{
    const int t0 = blockIdx.x * 4, bidx = blockIdx.y, d = threadIdx.x;
    float wk9[9], wv9[9];
    #pragma unroll
    for (int i = 0; i < 9; i++) { wk9[i] = wk[d * 9 + i]; wv9[i] = wv[d * 9 + i]; }
    const float sck = bgk[d] * rsqrtf(1.0f + EPS_BN);
    const float scv = bgv[d] * rsqrtf(1.0f + EPS_BN);
    const float cbkd = cbk[d], bbkd = bbk[d], cbvd = cbv[d], bbvd = bbv[d];

    #pragma unroll
    for (int ti = 0; ti < 4; ti++) {
        const int t = t0 + ti;
        int hwin, hwout, loc, base;
        if (t < 256) { hwin = 32; hwout = 16; loc = t;       base = 0;   }
        else         { hwin = 16; hwout = 8;  loc = t - 256; base = CNS; }
        const int oy = loc / hwout, ox = loc % hwout;

        float sk = 0.f, sv = 0.f;
        #pragma unroll
        for (int ky = 0; ky < 3; ky++) {
            const int iy = 2 * oy + ky - 1;
            if ((unsigned)iy >= (unsigned)hwin) continue;
            #pragma unroll
            for (int kx = 0; kx < 3; kx++) {
                const int ix = 2 * ox + kx - 1;
                if ((unsigned)ix >= (unsigned)hwin) continue;
                const float xv = xn[((size_t)bidx * CN + base + iy * hwin + ix) * CD + d];
                sk += wk9[ky * 3 + kx] * xv;
                sv += wv9[ky * 3 + kx] * xv;
            }
        }
        const size_t o = ((size_t)bidx * CKV + t) * CD + d;
        outk[o] = tf32r((sk + cbkd) * sck + bbkd);
        outv[o] = tf32r((sv + cbvd) * scv + bbvd);
    }
}

// ---------------- launch ----------------
extern "C" void kernel_launch(void* const* d_in, const int* in_sizes, int n_in,
                              void* d_out, int out_size)
{
    const float* x     = (const float*)d_in[0];
    const float* ln1_g = (const float*)d_in[1];
    const float* ln1_b = (const float*)d_in[2];
    const float* dwq_w = (const float*)d_in[3];
    const float* dwq_b = (const float*)d_in[4];
    const float* bnq_g = (const float*)d_in[5];
    const float* bnq_b = (const float*)d_in[6];
    const float* dwk_w = (const float*)d_in[7];
    const float* dwk_b = (const float*)d_in[8];
    const float* bnk_g = (const float*)d_in[9];
    const float* bnk_b = (const float*)d_in[10];
    const float* dwv_w = (const float*)d_in[11];
    const float* dwv_b = (const float*)d_in[12];
    const float* bnv_g = (const float*)d_in[13];
    const float* bnv_b = (const float*)d_in[14];
    const float* pq_w  = (const float*)d_in[15];
    const float* pq_b  = (const float*)d_in[16];
    const float* pk_w  = (const float*)d_in[17];
    const float* pk_b  = (const float*)d_in[18];
    const float* pv_w  = (const float*)d_in[19];
    const float* pv_b  = (const float*)d_in[20];
    const float* ln2_g = (const float*)d_in[21];
    const float* ln2_b = (const float*)d_in[22];
    const float* ff1_w = (const float*)d_in[23];
    const float* ff1_b = (const float*)d_in[24];
    const float* ff2_w = (const float*)d_in[25];
    const float* ff2_b = (const float*)d_in[26];
    float* out = (float*)d_out;

    float *xn, *qc, *kc, *vc, *qpb, *kpb, *vpb, *attnb, *x2b, *hb, *ffb;
    float *wpq, *wpk, *wpv, *wf1, *wf2;
    cudaGetSymbolAddress((void**)&xn,    g_xn);
    cudaGetSymbolAddress((void**)&qc,    g_qc);
    cudaGetSymbolAddress((void**)&kc,    g_kc);
    cudaGetSymbolAddress((void**)&vc,    g_vc);
    cudaGetSymbolAddress((void**)&qpb,   g_qp);
    cudaGetSymbolAddress((void**)&kpb,   g_kp);
    cudaGetSymbolAddress((void**)&vpb,   g_vp);
    cudaGetSymbolAddress((void**)&attnb, g_attn);
    cudaGetSymbolAddress((void**)&x2b,   g_x2);
    cudaGetSymbolAddress((void**)&hb,    g_h);
    cudaGetSymbolAddress((void**)&ffb,   g_ff);
    cudaGetSymbolAddress((void**)&wpq,   g_wpq);
    cudaGetSymbolAddress((void**)&wpk,   g_wpk);
    cudaGetSymbolAddress((void**)&wpv,   g_wpv);
    cudaGetSymbolAddress((void**)&wf1,   g_wf1);
    cudaGetSymbolAddress((void**)&wf2,   g_wf2);

    cudaFuncSetAttribute(qkv_kernel,  cudaFuncAttributeMaxDynamicSharedMemorySize, GSMEM_BYTES);
    cudaFuncSetAttribute(gemm_mma<1>, cudaFuncAttributeMaxDynamicSharedMemorySize, GSMEM_BYTES);
    cudaFuncSetAttribute(gemm_mma<2>, cudaFuncAttributeMaxDynamicSharedMemorySize, GSMEM_BYTES);
    cudaFuncSetAttribute(attn_mma_kernel, cudaFuncAttributeMaxDynamicSharedMemorySize, ATT_SMEM_BYTES);

    // 0. round weights to tf32 (one launch)
    {
        const int n01 = CD * CD, n3 = CFF * CD, n4 = CD * CFF;
        const int total = 3 * n01 + n3 + n4;
        round5_kernel<<<(total + 255) / 256, 256>>>(
            pq_w, wpq, n01, pk_w, wpk, n01, pv_w, wpv, n01,
            ff1_w, wf1, n3, ff2_w, wf2, n4);
    }

    // 1. LN1
    ln1_kernel<<<CB * CN, 128>>>(x, ln1_g, ln1_b, xn);

    // 2. depthwise convs (4 tokens per block, outputs tf32-rounded)
    convq_kernel<<<dim3(CN / 4, CB), CD>>>(xn, dwq_w, dwq_b, bnq_g, bnq_b, qc);
    convkv_kernel<<<dim3(CKV / 4, CB), CD>>>(xn, dwk_w, dwk_b, bnk_g, bnk_b,
                                             dwv_w, dwv_b, bnv_g, bnv_b, kc, vc);

    // 3. fused Q/K/V projections (proven 2-stage mma.sync tf32)
    qkv_kernel<<<dim3(3, 480), 256, GSMEM_BYTES>>>(
        qc, kc, vc, wpq, wpk, wpv, pq_b, pk_b, pv_b, qpb, kpb, vpb);

    // 4. flash attention (single merged launch)
    attn_mma_kernel<<<dim3(10, CH, CB), 256, ATT_SMEM_BYTES>>>(qpb, kpb, vpb, attnb);

    // 5. residual + LN2
    addln2_kernel<<<CB * CN, 128>>>(x, attnb, ln2_g, ln2_b, x2b, hb);

    // 6. FFN (mma.sync tf32)
    gemm_mma<1><<<dim3(CFF / 128, CB * CN / 128), 256, GSMEM_BYTES>>>(
        hb, wf1, ff1_b, nullptr, ffb, CFF, CD);
    gemm_mma<2><<<dim3(CD / 128, CB * CN / 128), 256, GSMEM_BYTES>>>(
        ffb, wf2, ff2_b, x2b, out, CD, CFF);
}